// round 7
// baseline (speedup 1.0000x reference)
#include <cuda_runtime.h>

// Problem constants
#define BATCH 16
#define SEQ   720
#define CIN   321
#define NORD  64
#define PRED  720
#define M_TOT (BATCH*CIN)        // 5136
#define MPAD  5248               // 41 * 128
#define TSPLIT 9
#define TCHUNK 80                // 720/9
#define KCH   20                 // k-chunk in gemm1 (4 per TCHUNK)
#define ROW_STRIDE (SEQ*CIN)     // 231120
#define TSTRIDE 68               // padded transpose stride (floats)
#define NCHAIN 32                // chains in buildk (A^32 stride)

typedef unsigned long long ull;

// ---------------- packed f32x2 helpers ----------------
__device__ __forceinline__ ull fma2(ull a, ull b, ull c) {
    ull d;
    asm("fma.rn.f32x2 %0, %1, %2, %3;" : "=l"(d) : "l"(a), "l"(b), "l"(c));
    return d;
}
__device__ __forceinline__ ull dup2(float x) {
    ull d; asm("mov.b64 %0, {%1, %1};" : "=l"(d) : "f"(x)); return d;
}
__device__ __forceinline__ float2 upk2(ull v) {
    float x, y; asm("mov.b64 {%0, %1}, %2;" : "=f"(x), "=f"(y) : "l"(v));
    return make_float2(x, y);
}

// ---------------- device scratch ----------------
__device__ float g_Kt   [PRED*NORD];        // Kt[t][n] = (A^(719-t) B)[n]
__device__ float g_Spart[NCHAIN*NORD];
__device__ float g_EWT  [NORD*PRED];        // (E @ W) transposed: [n][p]
__device__ float g_eb   [PRED];             // E @ b_mlp
__device__ float g_XK   [TSPLIT][MPAD*NORD];
__device__ float g_XKpT [NORD*MPAD];        // alpha-folded GEMM2 operand, [n][m]
__device__ float g_rsum [TSPLIT][MPAD];
__device__ float g_rsq  [TSPLIT][MPAD];
__device__ float g_mean [MPAD];
__device__ float g_std  [MPAD];

// ============================================================================
// buildk: blocks 0..31 each redundantly square A -> A^2..A^32 (+transposes),
// build their seed A^r B via binary decomposition (<=5 matvecs), then run a
// 23-step chain with A^32 writing Kt rows s = 32j + r.
// Blocks 32..47 compute EWT = (E @ W)^T and eb = E @ b.
// ============================================================================
__global__ void __launch_bounds__(256) buildk_kernel(
    const float* __restrict__ A, const float* __restrict__ Bv,
    const float* __restrict__ E, const float* __restrict__ W,
    const float* __restrict__ bm)
{
    extern __shared__ float sh[];
    const int tid = threadIdx.x;
    const int bid = blockIdx.x;

    if (bid >= NCHAIN) {
        // ---------------- EWT / eb blocks ----------------
        float* Wsh = sh;               // 4096
        float* Esh = sh + 4096;        // 45*64
        __shared__ float bsh[NORD];
        const int e = bid - NCHAIN;
        for (int i = tid; i < NORD*NORD; i += 256) Wsh[i] = W[i];
        for (int i = tid; i < 45*NORD; i += 256)  Esh[i] = E[e*45*NORD + i];
        if (tid < NORD) bsh[tid] = bm[tid];
        __syncthreads();
        for (int idx = tid; idx < 45*NORD; idx += 256) {
            const int pl = idx >> 6, m = idx & 63;
            float a0 = 0.f, a1 = 0.f;
#pragma unroll
            for (int n = 0; n < NORD; n += 2) {
                a0 += Esh[pl*NORD + n    ] * Wsh[(n    )*NORD + m];
                a1 += Esh[pl*NORD + n + 1] * Wsh[(n + 1)*NORD + m];
            }
            g_EWT[(size_t)m*PRED + e*45 + pl] = a0 + a1;
        }
        if (tid < 45) {
            float a = 0.f;
#pragma unroll
            for (int n = 0; n < NORD; n++) a += Esh[tid*NORD + n] * bsh[n];
            g_eb[e*45 + tid] = a;
        }
        return;
    }

    // ---------------- chain blocks ----------------
    float* TP[6];
#pragma unroll
    for (int i = 0; i < 6; i++) TP[i] = sh + i * NORD * TSTRIDE;
    float* N0 = sh + 6 * NORD * TSTRIDE;
    float* N1 = N0 + NORD*NORD;
    __shared__ float vsh[NORD];
    __shared__ float pb[256];

    for (int i = tid; i < NORD*NORD; i += 256) N0[i] = A[i];
    __syncthreads();
    for (int i = tid; i < NORD*NORD; i += 256)
        TP[0][(i & 63)*TSTRIDE + (i >> 6)] = N0[i];
    __syncthreads();

    // 5 squarings: A^2 .. A^32
    float* srcN = N0;
    float* dstN = N1;
    const int ig = tid >> 4;
    const int jg = tid & 15;
#pragma unroll
    for (int s = 0; s < 5; s++) {
        const float* srcT = TP[s];
        ull acc2[4][2];
#pragma unroll
        for (int ii = 0; ii < 4; ii++) { acc2[ii][0] = 0ull; acc2[ii][1] = 0ull; }
#pragma unroll 8
        for (int k = 0; k < NORD; k++) {
            const float4 a = *(const float4*)&srcT[k*TSTRIDE + ig*4];
            const ulonglong2 b = *(const ulonglong2*)&srcN[k*NORD + jg*4];
            float av[4] = {a.x, a.y, a.z, a.w};
#pragma unroll
            for (int ii = 0; ii < 4; ii++) {
                const ull am = dup2(av[ii]);
                acc2[ii][0] = fma2(am, b.x, acc2[ii][0]);
                acc2[ii][1] = fma2(am, b.y, acc2[ii][1]);
            }
        }
#pragma unroll
        for (int ii = 0; ii < 4; ii++) {
            const float2 lo = upk2(acc2[ii][0]);
            const float2 hi = upk2(acc2[ii][1]);
            float4 v; v.x = lo.x; v.y = lo.y; v.z = hi.x; v.w = hi.y;
            *(float4*)&dstN[(ig*4 + ii)*NORD + jg*4] = v;
        }
        __syncthreads();
        for (int i = tid; i < NORD*NORD; i += 256)
            TP[s+1][(i & 63)*TSTRIDE + (i >> 6)] = dstN[i];
        __syncthreads();
        float* tmp = srcN; srcN = dstN; dstN = tmp;
    }

    const int r = bid;
    const int n = tid & 63, q = tid >> 6;

    // seed: v = A^r B via binary decomposition of r (bits 0..4)
    if (tid < NORD) vsh[tid] = Bv[tid];
    __syncthreads();
#pragma unroll
    for (int b = 0; b < 5; b++) {
        if ((r >> b) & 1) {
            float p = 0.f;
#pragma unroll
            for (int kk = 0; kk < 16; kk++) {
                const int k = q*16 + kk;
                p += TP[b][k*TSTRIDE + n] * vsh[k];
            }
            pb[tid] = p;
            __syncthreads();
            if (tid < NORD) vsh[tid] = pb[tid] + pb[tid+64] + pb[tid+128] + pb[tid+192];
            __syncthreads();
        }
    }

    // chain: steps with M = A^32; emit s = 32j + r (< 720)
    const float* T32 = TP[5];
    float sacc = 0.f;
    for (int j = 0; j < 23; j++) {
        const int s_exp = 32*j + r;
        if (s_exp < 720 && tid < NORD) {
            const float u = vsh[tid];
            g_Kt[(719 - s_exp)*NORD + tid] = u;
            sacc += u;
        }
        if (j < 22) {
            float p = 0.f;
#pragma unroll
            for (int kk = 0; kk < 16; kk++) {
                const int k = q*16 + kk;
                p += T32[k*TSTRIDE + n] * vsh[k];
            }
            pb[tid] = p;
            __syncthreads();
            if (tid < NORD) vsh[tid] = pb[tid] + pb[tid+64] + pb[tid+128] + pb[tid+192];
            __syncthreads();
        }
    }
    if (tid < NORD) g_Spart[r*NORD + tid] = sacc;
}

// ============================================================================
// GEMM1: XK[m,n] = sum_t x_raw[m,t] * Kt[t,n], fused mean/var partials.
// grid (41, 9), block 256. Mtile=128, N=64. Per thread 8m x 4n as 4 m-pairs.
// ============================================================================
__global__ void __launch_bounds__(256) gemm1_kernel(const float* __restrict__ x) {
    __shared__ __align__(16) float Xs[KCH][128];
    __shared__ __align__(16) float Ks[KCH][64];
    __shared__ float sred[256];
    __shared__ float sqred[256];

    const int tid   = threadIdx.x;
    const int mbase = blockIdx.x * 128;
    const int h     = blockIdx.y;
    const int t0    = h * TCHUNK;

    const int mm   = tid & 127;   // load column (m within tile)
    const int trow = tid >> 7;    // 0/1
    const int m_load = mbase + mm;
    const int bidx   = m_load / CIN;
    const int chl    = m_load - bidx * CIN;
    const float* xrow = x + (size_t)bidx * ROW_STRIDE + chl;
    const bool mval   = (m_load < M_TOT);

    const int tn = tid & 15;      // n = tn*4 + ni
    const int tm = tid >> 4;      // m = mbase + tm*8 + ...

    ull acc[4][4];                // [m-pair][n]
#pragma unroll
    for (int i = 0; i < 4; i++)
#pragma unroll
        for (int j = 0; j < 4; j++) acc[i][j] = 0ull;
    float psum = 0.f, psq = 0.f;

    for (int kt = 0; kt < TCHUNK/KCH; kt++) {
        const int tb = t0 + kt*KCH;
        // load X: 10 rows per thread (tt = trow + 2i)
#pragma unroll
        for (int i = 0; i < KCH/2; i++) {
            const int tt = trow + 2*i;
            float xv = mval ? xrow[(tb + tt) * CIN] : 0.f;
            Xs[tt][mm] = xv;
            psum += xv;
            psq  += xv * xv;
        }
        // load K: 5 per thread
#pragma unroll
        for (int i = 0; i < (KCH*64)/256; i++) {
            const int idx = tid + i*256;
            const int tt = idx >> 6, nn = idx & 63;
            Ks[tt][nn] = g_Kt[(tb + tt) * NORD + nn];
        }
        __syncthreads();
#pragma unroll
        for (int tt = 0; tt < KCH; tt++) {
            const ulonglong2 a0 = *(const ulonglong2*)&Xs[tt][tm*8];
            const ulonglong2 a1 = *(const ulonglong2*)&Xs[tt][tm*8 + 4];
            const float4 b = *(const float4*)&Ks[tt][tn*4];
            const ull ap[4] = {a0.x, a0.y, a1.x, a1.y};
            const ull bd[4] = {dup2(b.x), dup2(b.y), dup2(b.z), dup2(b.w)};
#pragma unroll
            for (int mp = 0; mp < 4; mp++)
#pragma unroll
                for (int ni = 0; ni < 4; ni++)
                    acc[mp][ni] = fma2(ap[mp], bd[ni], acc[mp][ni]);
        }
        __syncthreads();
    }

    float* xk = g_XK[h];
#pragma unroll
    for (int mp = 0; mp < 4; mp++) {
        const int m0 = mbase + tm*8 + mp*2;
        const float2 c0 = upk2(acc[mp][0]);
        const float2 c1 = upk2(acc[mp][1]);
        const float2 c2 = upk2(acc[mp][2]);
        const float2 c3 = upk2(acc[mp][3]);
        float4 r0; r0.x = c0.x; r0.y = c1.x; r0.z = c2.x; r0.w = c3.x;
        float4 r1; r1.x = c0.y; r1.y = c1.y; r1.z = c2.y; r1.w = c3.y;
        *(float4*)&xk[(size_t)m0 * NORD + tn*4]       = r0;
        *(float4*)&xk[(size_t)(m0+1) * NORD + tn*4]   = r1;
    }
    sred[tid]  = psum;
    sqred[tid] = psq;
    __syncthreads();
    if (tid < 128) {
        g_rsum[h][mbase + tid] = sred[tid] + sred[tid + 128];
        g_rsq [h][mbase + tid] = sqred[tid] + sqred[tid + 128];
    }
}

// ============================================================================
// fuse: reduce t-split partials + stats + S + alpha/beta fold + transpose.
// XKpT[n, m] = alpha_m * sum_h XK[h][m,n] + beta_m * S[n]
// grid 82, block 256 (64 m per block).
// ============================================================================
__global__ void __launch_bounds__(256) fuse_kernel(const float* __restrict__ aw,
                                                   const float* __restrict__ ab) {
    __shared__ float TT[64*65];
    __shared__ float alpha_s[64], beta_s[64], Ssh[64];
    const int tid = threadIdx.x;
    const int mb  = blockIdx.x * 64;

    if (tid < 64) {
        const int m = mb + tid;
        float s = 0.f, qq = 0.f;
#pragma unroll
        for (int h = 0; h < TSPLIT; h++) { s += g_rsum[h][m]; qq += g_rsq[h][m]; }
        const float mean = s * (1.0f / 720.0f);
        const float var  = qq * (1.0f / 720.0f) - mean * mean;
        const float sd   = sqrtf(var + 1e-5f);
        const int bidx = m / CIN;
        const int ch   = m - bidx * CIN;
        const float al = aw[ch] / sd;
        alpha_s[tid] = al;
        beta_s[tid]  = ab[ch] - mean * al;
        g_mean[m] = mean;
        g_std[m]  = sd;
    } else if (tid < 128) {
        const int nn = tid - 64;
        float s = 0.f;
#pragma unroll
        for (int rr = 0; rr < NCHAIN; rr++) s += g_Spart[rr*NORD + nn];
        Ssh[nn] = s;
    }
    __syncthreads();

#pragma unroll
    for (int i = 0; i < 16; i++) {
        const int idx = i*256 + tid;           // 0..4095
        const int ml = idx >> 6, nn = idx & 63;
        float v = 0.f;
#pragma unroll
        for (int h = 0; h < TSPLIT; h++) v += g_XK[h][(size_t)(mb + ml)*NORD + nn];
        TT[nn*65 + ml] = alpha_s[ml]*v + beta_s[ml]*Ssh[nn];
    }
    __syncthreads();
#pragma unroll
    for (int i = 0; i < 16; i++) {
        const int idx = i*256 + tid;
        const int nn = idx >> 6, ml = idx & 63;
        g_XKpT[(size_t)nn*MPAD + mb + ml] = TT[nn*65 + ml];
    }
}

// ============================================================================
// GEMM2 + epilogue: pre[m,p] = sum_n XKpT[n,m] EWT[n,p] + eb[p];
// out[b,p,ch] = (pre - ab)/(aw+1e-10) * sd + mean. Coalesced stores via smem.
// grid (82, 6), block 256. Mtile=64, Ptile=128, K=64 resident.
// Per thread 8m x 4p as 4 m-pairs (a-operand = direct 64-bit smem pair).
// ============================================================================
__global__ void __launch_bounds__(256) gemm2_kernel(float* __restrict__ out,
                                                    const float* __restrict__ aw,
                                                    const float* __restrict__ ab) {
    __shared__ __align__(16) float pool[12288];   // 48 KB
    float* Xs = pool;          // [64 k][64 m]
    float* Es = pool + 4096;   // [64 k][128 p]

    const int tid   = threadIdx.x;
    const int mbase = blockIdx.x * 64;
    const int pbase = blockIdx.y * 128;
    const int tm = tid & 7;      // m = mbase + tm*8 + ...
    const int tp = tid >> 3;     // p = pbase + tp*4 + pi   (tp 0..31)

    // stage Xs: coalesced, 4 float4 per thread
#pragma unroll
    for (int i = 0; i < 4; i++) {
        const int idx = tid + i*256;            // 0..1023
        const int n = idx >> 4, mg = idx & 15;
        *(float4*)&Xs[n*64 + mg*4] =
            *(const float4*)&g_XKpT[(size_t)n*MPAD + mbase + mg*4];
    }
    // stage Es with p guard: 8 float4 per thread
#pragma unroll
    for (int i = 0; i < 8; i++) {
        const int idx = tid + i*256;            // 0..2047
        const int n = idx >> 5, pg = idx & 31;
        const int p = pbase + pg*4;
        float4 v = make_float4(0.f, 0.f, 0.f, 0.f);
        if (p < PRED) v = *(const float4*)&g_EWT[(size_t)n*PRED + p];
        *(float4*)&Es[n*128 + pg*4] = v;
    }
    __syncthreads();

    ull acc[4][4];               // [m-pair][pi]
#pragma unroll
    for (int i = 0; i < 4; i++)
#pragma unroll
        for (int j = 0; j < 4; j++) acc[i][j] = 0ull;

#pragma unroll 16
    for (int k = 0; k < 64; k++) {
        const ulonglong2 a0 = *(const ulonglong2*)&Xs[k*64 + tm*8];
        const ulonglong2 a1 = *(const ulonglong2*)&Xs[k*64 + tm*8 + 4];
        const float4 b = *(const float4*)&Es[k*128 + tp*4];
        const ull ap[4] = {a0.x, a0.y, a1.x, a1.y};
        const ull bd[4] = {dup2(b.x), dup2(b.y), dup2(b.z), dup2(b.w)};
#pragma unroll
        for (int mp = 0; mp < 4; mp++)
#pragma unroll
            for (int pi = 0; pi < 4; pi++)
                acc[mp][pi] = fma2(ap[mp], bd[pi], acc[mp][pi]);
    }
    __syncthreads();   // done reading Xs/Es; pool reused as Os

    // epilogue staged into Os[p_loc][m_loc] (stride 68)
    float* Os = pool;            // 128*68 = 8704 floats
    float ebv[4];
#pragma unroll
    for (int pi = 0; pi < 4; pi++) {
        const int p = pbase + tp*4 + pi;
        ebv[pi] = (p < PRED) ? g_eb[p] : 0.f;
    }
#pragma unroll
    for (int mp = 0; mp < 4; mp++) {
        const int mloc0 = tm*8 + mp*2;
        const float2 c[4] = {upk2(acc[mp][0]), upk2(acc[mp][1]),
                             upk2(acc[mp][2]), upk2(acc[mp][3])};
#pragma unroll
        for (int w = 0; w < 2; w++) {
            const int m = mbase + mloc0 + w;
            const float mean = g_mean[m];
            const float sd   = g_std[m];
            const int bi = m / CIN;
            const int ch = m - bi * CIN;
            const float abv = ab[ch];
            const float scale = sd / (aw[ch] + 1e-10f);
#pragma unroll
            for (int pi = 0; pi < 4; pi++) {
                const float val = w ? c[pi].y : c[pi].x;
                Os[(tp*4 + pi)*68 + mloc0 + w] = (val + ebv[pi] - abv) * scale + mean;
            }
        }
    }
    __syncthreads();

    // coalesced global store: lanes sweep m, loop sweeps p
    const int ml = tid & 63;
    const int ph = tid >> 6;            // 0..3
    const int m  = mbase + ml;
    if (m < M_TOT) {
        const int bi = m / CIN;
        const int ch = m - bi * CIN;
        float* ob = out + (size_t)bi * ROW_STRIDE + ch;
        const int plim = (PRED - pbase < 128) ? (PRED - pbase) : 128;
        for (int pl = ph; pl < plim; pl += 4)
            ob[(size_t)(pbase + pl) * CIN] = Os[pl*68 + ml];
    }
}

// ---------------- launcher: 4 graph nodes ----------------
extern "C" void kernel_launch(void* const* d_in, const int* in_sizes, int n_in,
                              void* d_out, int out_size) {
    (void)in_sizes; (void)n_in; (void)out_size;
    const float* x  = (const float*)d_in[0];   // x_enc (16,720,321)
    const float* A  = (const float*)d_in[1];   // A (64,64)
    const float* Bv = (const float*)d_in[2];   // B_vec (64)
    const float* E  = (const float*)d_in[3];   // eval_matrix (720,64)
    const float* W  = (const float*)d_in[4];   // W_mlp (64,64)
    const float* bm = (const float*)d_in[5];   // b_mlp (64)
    const float* aw = (const float*)d_in[6];   // affine_weight (321)
    const float* ab = (const float*)d_in[7];   // affine_bias (321)
    float* out = (float*)d_out;

    const int buildk_smem = (6*NORD*TSTRIDE + 2*NORD*NORD) * (int)sizeof(float); // 137216
    cudaFuncSetAttribute(buildk_kernel, cudaFuncAttributeMaxDynamicSharedMemorySize, buildk_smem);

    buildk_kernel<<<NCHAIN + 16, 256, buildk_smem>>>(A, Bv, E, W, bm);
    gemm1_kernel<<<dim3(MPAD/128, TSPLIT), 256>>>(x);
    fuse_kernel<<<MPAD/64, 256>>>(aw, ab);
    gemm2_kernel<<<dim3(MPAD/64, 6), 256>>>(out, aw, ab);
}